// round 10
// baseline (speedup 1.0000x reference)
#include <cuda_runtime.h>
#include <cstdint>

// ---------------------------------------------------------------------------
// BinaryConnectNet forward (compute_103-safe: mma.sync/ldmatrix/cp.async only)
//  conv1: dw3x3(g=3)+pw1x1(3->128), sign, maxpool2   -> a1 [1024][256pix][128c] int8
//  conv2: dw3x3(g=128)+pw1x1(128->256), sign, pool2  -> a2 [1024][16384] int8
//  fc1:   W quantized to 28-bit fixed point, split into 4 int8 digit planes;
//         ONE s8 IMMA GEMM [1024 x 4096 x 16384] -> exact s32 partials
//         -> exact recombine + bias + sign -> a3 int8
//  fc2:   a3 @ W2^T + b2 -> out [1024][10] fp32
// ---------------------------------------------------------------------------

__device__ int8_t g_a1[1024 * 256 * 128];
__device__ int8_t g_a2[1024 * 16384];
__device__ int8_t g_a3[1024 * 1024];
__device__ int8_t g_w1d[4096ull * 16384];      // [p*1024+j][k] digit planes
__device__ int    g_s32[4ull * 1024 * 1024];   // [p][m][j] s32 partials

__device__ __forceinline__ float fsign(float v) {
    return (v > 0.f) ? 1.f : ((v < 0.f) ? -1.f : 0.f);
}
__device__ __forceinline__ int isign(int v) { return (v > 0) - (v < 0); }

__device__ __forceinline__ uint32_t smem_u32(const void* p) {
    uint32_t a;
    asm("{ .reg .u64 t; cvta.to.shared.u64 t, %1; cvt.u32.u64 %0, t; }"
        : "=r"(a) : "l"(p));
    return a;
}
__device__ __forceinline__ void cp16(uint32_t dst, const void* src) {
    asm volatile("cp.async.cg.shared.global [%0], [%1], 16;"
                 :: "r"(dst), "l"(src) : "memory");
}
__device__ __forceinline__ void ldsm4(uint32_t* r, uint32_t addr) {
    asm volatile("ldmatrix.sync.aligned.m8n8.x4.shared.b16 {%0,%1,%2,%3}, [%4];"
                 : "=r"(r[0]), "=r"(r[1]), "=r"(r[2]), "=r"(r[3]) : "r"(addr));
}
__device__ __forceinline__ void imma(int* c, const uint32_t* a,
                                     uint32_t b0, uint32_t b1) {
    asm volatile("mma.sync.aligned.m16n8k32.row.col.s32.s8.s8.s32 "
                 "{%0,%1,%2,%3}, {%4,%5,%6,%7}, {%8,%9}, {%0,%1,%2,%3};"
                 : "+r"(c[0]), "+r"(c[1]), "+r"(c[2]), "+r"(c[3])
                 : "r"(a[0]), "r"(a[1]), "r"(a[2]), "r"(a[3]),
                   "r"(b0), "r"(b1));
}

// ---------------------------------------------------------------------------
// Kernel 1: conv1 dw + pw + sign + maxpool, one image per block.
// ---------------------------------------------------------------------------
__global__ __launch_bounds__(256) void k_conv1(
    const float* __restrict__ x,
    const float* __restrict__ w1dw, const float* __restrict__ b1dw,
    const float* __restrict__ w1pw, const float* __restrict__ b1pw)
{
    __shared__ float sx[3][32][32];
    __shared__ float sdw[3][32][32];
    __shared__ float swdw[27];
    __shared__ float sbdw[3];
    __shared__ float swpw[128 * 3];
    __shared__ float sbpw[128];

    const int n = blockIdx.x, tid = threadIdx.x;

    for (int i = tid; i < 3072; i += 256) ((float*)sx)[i] = x[n * 3072 + i];
    if (tid < 27)  swdw[tid] = fsign(w1dw[tid]);
    if (tid < 3)   sbdw[tid] = fsign(b1dw[tid]);
    for (int i = tid; i < 384; i += 256) swpw[i] = fsign(w1pw[i]);
    if (tid < 128) sbpw[tid] = fsign(b1pw[tid]);
    __syncthreads();

    for (int i = tid; i < 3072; i += 256) {
        int c = i >> 10, p = i & 1023, y = p >> 5, xx = p & 31;
        float acc = 0.f;
#pragma unroll
        for (int ky = 0; ky < 3; ky++) {
#pragma unroll
            for (int kx = 0; kx < 3; kx++) {
                int yy = y + ky - 1, xw = xx + kx - 1;
                if (yy >= 0 && yy < 32 && xw >= 0 && xw < 32)
                    acc += swdw[c * 9 + ky * 3 + kx] * sx[c][yy][xw];
            }
        }
        acc += sbdw[c];
        ((float*)sdw)[i] = acc;
    }
    __syncthreads();

    for (int i = tid; i < 32768; i += 256) {
        int oc = i & 127, pp = i >> 7;
        int oy = pp >> 4, ox = pp & 15;
        float w0 = swpw[oc * 3 + 0], w1 = swpw[oc * 3 + 1],
              w2 = swpw[oc * 3 + 2], bb = sbpw[oc];
        float vmax = -1e30f;
#pragma unroll
        for (int d = 0; d < 4; d++) {
            int y = 2 * oy + (d >> 1), xw = 2 * ox + (d & 1);
            float v = w0 * sdw[0][y][xw] + w1 * sdw[1][y][xw]
                    + w2 * sdw[2][y][xw] + bb;
            vmax = fmaxf(vmax, v);
        }
        g_a1[n * 32768 + pp * 128 + oc] = (int8_t)(int)fsign(vmax);
    }
}

// ---------------------------------------------------------------------------
// Kernel 2: conv2 dw (int) + pw (dp4a) + sign + maxpool, one image per block.
// ---------------------------------------------------------------------------
__global__ __launch_bounds__(256) void k_conv2(
    const float* __restrict__ w2dw, const float* __restrict__ b2dw,
    const float* __restrict__ w2pw, const float* __restrict__ b2pw)
{
    extern __shared__ char sm[];
    int8_t* s_a1 = (int8_t*)sm;
    int8_t* s_t  = (int8_t*)(sm + 32768);
    int8_t* s_w  = (int8_t*)(sm + 65536);
    int8_t* s_wd = (int8_t*)(sm + 98304);
    int8_t* s_bd = (int8_t*)(sm + 99456);
    int8_t* s_bp = (int8_t*)(sm + 99584);

    const int n = blockIdx.x, tid = threadIdx.x;

    {
        const uint4* src = (const uint4*)(g_a1 + n * 32768);
        uint4* dst = (uint4*)s_a1;
        for (int i = tid; i < 2048; i += 256) dst[i] = src[i];
    }
    for (int i = tid; i < 1152; i += 256) s_wd[i] = (int8_t)(int)fsign(w2dw[i]);
    for (int i = tid; i < 32768; i += 256) s_w[i] = (int8_t)(int)fsign(w2pw[i]);
    if (tid < 128) s_bd[tid] = (int8_t)(int)fsign(b2dw[tid]);
    s_bp[tid] = (int8_t)(int)fsign(b2pw[tid]);
    __syncthreads();

    for (int i = tid; i < 32768; i += 256) {
        int c = i & 127, p = i >> 7, y = p >> 4, xx = p & 15;
        int acc = (int)s_bd[c];
#pragma unroll
        for (int ky = 0; ky < 3; ky++) {
#pragma unroll
            for (int kx = 0; kx < 3; kx++) {
                int yy = y + ky - 1, xw = xx + kx - 1;
                if (yy >= 0 && yy < 16 && xw >= 0 && xw < 16)
                    acc += (int)s_wd[c * 9 + ky * 3 + kx]
                         * (int)s_a1[(yy * 16 + xw) * 128 + c];
            }
        }
        s_t[p * 128 + c] = (int8_t)acc;
    }
    __syncthreads();

    {
        const int oc = tid;
        uint32_t wreg[32];
        const uint32_t* wsrc = (const uint32_t*)s_w + oc * 32;
#pragma unroll
        for (int j = 0; j < 32; j++) wreg[j] = wsrc[j];
        const int bb = (int)s_bp[oc];
        int8_t* s_a2 = s_a1;
        const uint4* t4 = (const uint4*)s_t;

        for (int q = 0; q < 64; q++) {
            int py = q >> 3, px = q & 7;
            int vmax = -2000000000;
#pragma unroll
            for (int d = 0; d < 4; d++) {
                int p = (2 * py + (d >> 1)) * 16 + 2 * px + (d & 1);
                int acc = bb;
#pragma unroll
                for (int jj = 0; jj < 8; jj++) {
                    uint4 t = t4[p * 8 + jj];
                    acc = __dp4a((int)t.x, (int)wreg[jj * 4 + 0], acc);
                    acc = __dp4a((int)t.y, (int)wreg[jj * 4 + 1], acc);
                    acc = __dp4a((int)t.z, (int)wreg[jj * 4 + 2], acc);
                    acc = __dp4a((int)t.w, (int)wreg[jj * 4 + 3], acc);
                }
                vmax = max(vmax, acc);
            }
            s_a2[oc * 64 + q] = (int8_t)isign(vmax);
        }
    }
    __syncthreads();

    {
        uint4* g = (uint4*)(g_a2 + n * 16384);
        const uint4* s2 = (const uint4*)s_a1;
        for (int i = tid; i < 1024; i += 256) g[i] = s2[i];
    }
}

// ---------------------------------------------------------------------------
// Kernel W: fc1_w -> 4 int8 digit planes of round(w * 2^32)  (base 128 digits)
// w = ((d0*128 + d1)*128 + d2)*128 + d3) * 2^-32  (+-2^-33 rounding)
// ---------------------------------------------------------------------------
__global__ __launch_bounds__(256) void k_wsplit(const float* __restrict__ W)
{
    const size_t idx4 = (size_t)blockIdx.x * 256 + threadIdx.x;  // float4 idx
    float4 w = ((const float4*)W)[idx4];
    const int j  = (int)(idx4 >> 12);        // 4096 float4 per row
    const int k  = ((int)idx4 & 4095) * 4;

    float wv[4] = {w.x, w.y, w.z, w.w};
    char d[4][4];
#pragma unroll
    for (int c = 0; c < 4; c++) {
        long long nl = __double2ll_rn((double)wv[c] * 4294967296.0);
        int n = (int)nl;                      // |n| < 2^28
        int m1 = (n + 64) >> 7;  int d3 = n - (m1 << 7);
        int m2 = (m1 + 64) >> 7; int d2 = m1 - (m2 << 7);
        int m3 = (m2 + 64) >> 7; int d1 = m2 - (m3 << 7);
        d[0][c] = (char)m3; d[1][c] = (char)d1;
        d[2][c] = (char)d2; d[3][c] = (char)d3;
    }
#pragma unroll
    for (int p = 0; p < 4; p++) {
        char4 o; o.x = d[p][0]; o.y = d[p][1]; o.z = d[p][2]; o.w = d[p][3];
        *(char4*)(g_w1d + ((size_t)((p << 10) + j) << 14) + k) = o;
    }
}

// ---------------------------------------------------------------------------
// Kernel 3: fc1 IMMA GEMM  S[1024m][4096n'] = a2 @ Wdigits^T  (s8 x s8 -> s32)
// CTA: 128m x 256n, BK=128, 4-stage cp.async (192KB), 8 warps of 64x64.
// ---------------------------------------------------------------------------
static constexpr int ST_A  = 16384;     // 128 rows * 128B
static constexpr int ST_SZ = 49152;     // + 256 rows * 128B for B

__device__ __forceinline__ void gemm_load_stage(
    uint32_t stage, const int8_t* Ag, const int8_t* Bg, int kt, int tid)
{
    const int k0 = kt << 7;
#pragma unroll
    for (int r = 0; r < 4; r++) {           // A: 1024 chunks
        int c = tid + (r << 8);
        int row = c >> 3, seg = (c & 7) << 4;
        uint32_t dst = stage + row * 128 + (seg ^ ((row & 7) << 4));
        cp16(dst, Ag + (size_t)row * 16384 + k0 + seg);
    }
#pragma unroll
    for (int r = 0; r < 8; r++) {           // B: 2048 chunks
        int c = tid + (r << 8);
        int row = c >> 3, seg = (c & 7) << 4;
        uint32_t dst = stage + ST_A + row * 128 + (seg ^ ((row & 7) << 4));
        cp16(dst, Bg + (size_t)row * 16384 + k0 + seg);
    }
}

__global__ __launch_bounds__(256, 1) void k_fc1imma()
{
    extern __shared__ char sm[];
    const uint32_t smb = smem_u32(sm);

    const int tid = threadIdx.x, wid = tid >> 5, l = tid & 31;
    const int n0 = blockIdx.x * 256, m0 = blockIdx.y * 128;
    const int warp_m = wid & 1, warp_n = wid >> 1;

    const int8_t* Ag = g_a2 + (size_t)m0 * 16384;
    const int8_t* Bg = g_w1d + (size_t)n0 * 16384;

    // per-lane ldmatrix address components
    const int rowA = l & 15;
    const uint32_t cA = (uint32_t)(((l >> 4) << 4) ^ ((l & 7) << 4));
    const int rowB = (l & 7) + ((l >> 4) << 3);
    const uint32_t cB = (uint32_t)((((l >> 3) & 1) << 4) ^ ((l & 7) << 4));
    const uint32_t aBase = (uint32_t)((warp_m * 64 + rowA) * 128);
    const uint32_t bBase = (uint32_t)(ST_A + (warp_n * 64 + rowB) * 128);

    int c[4][8][4];
#pragma unroll
    for (int i = 0; i < 4; i++)
#pragma unroll
        for (int nn = 0; nn < 8; nn++)
#pragma unroll
            for (int q = 0; q < 4; q++) c[i][nn][q] = 0;

    gemm_load_stage(smb + 0 * ST_SZ, Ag, Bg, 0, tid);
    asm volatile("cp.async.commit_group;" ::: "memory");
    gemm_load_stage(smb + 1 * ST_SZ, Ag, Bg, 1, tid);
    asm volatile("cp.async.commit_group;" ::: "memory");
    gemm_load_stage(smb + 2 * ST_SZ, Ag, Bg, 2, tid);
    asm volatile("cp.async.commit_group;" ::: "memory");

    for (int it = 0; it < 128; it++) {
        asm volatile("cp.async.wait_group 2;" ::: "memory");
        __syncthreads();
        if (it + 3 < 128)
            gemm_load_stage(smb + ((it + 3) & 3) * ST_SZ, Ag, Bg, it + 3, tid);
        asm volatile("cp.async.commit_group;" ::: "memory");

        const uint32_t buf = smb + (it & 3) * ST_SZ;
#pragma unroll
        for (int kk = 0; kk < 4; kk++) {
            const uint32_t ka = ((uint32_t)(kk << 5)) ^ cA;
            const uint32_t kb = ((uint32_t)(kk << 5)) ^ cB;
            uint32_t a[4][4], b[4][4];
#pragma unroll
            for (int i = 0; i < 4; i++)
                ldsm4(a[i], buf + aBase + i * 2048 + ka);
#pragma unroll
            for (int t = 0; t < 4; t++)
                ldsm4(b[t], buf + bBase + t * 2048 + kb);
#pragma unroll
            for (int i = 0; i < 4; i++)
#pragma unroll
                for (int t = 0; t < 4; t++) {
                    imma(c[i][2 * t],     a[i], b[t][0], b[t][1]);
                    imma(c[i][2 * t + 1], a[i], b[t][2], b[t][3]);
                }
        }
    }
    __syncthreads();

    // epilogue: frags -> smem [128][260] -> coalesced global
    int* so = (int*)sm;
    const int gm = l >> 2, gn = (l & 3) << 1;
#pragma unroll
    for (int i = 0; i < 4; i++) {
        int ml = warp_m * 64 + i * 16 + gm;
#pragma unroll
        for (int nn = 0; nn < 8; nn++) {
            int nl = warp_n * 64 + nn * 8 + gn;
            so[ml * 260 + nl]           = c[i][nn][0];
            so[ml * 260 + nl + 1]       = c[i][nn][1];
            so[(ml + 8) * 260 + nl]     = c[i][nn][2];
            so[(ml + 8) * 260 + nl + 1] = c[i][nn][3];
        }
    }
    __syncthreads();
    {
        const int plane = n0 >> 10, jb = n0 & 1023;
        int* gp = g_s32 + ((size_t)plane << 20) + (size_t)m0 * 1024 + jb;
        for (int i = tid; i < 32768; i += 256) {
            int ml = i >> 8, nl = i & 255;
            gp[(size_t)ml * 1024 + nl] = so[ml * 260 + nl];
        }
    }
}

// ---------------------------------------------------------------------------
// Kernel 3b: exact recombine of 4 digit planes + bias, sign -> a3 int8
// ---------------------------------------------------------------------------
__global__ __launch_bounds__(256) void k_fc1red(const float* __restrict__ bf)
{
    const int n = blockIdx.x, t = threadIdx.x;
    const int4 s0 = ((const int4*)(g_s32 + (size_t)n * 1024))[t];
    const int4 s1 = ((const int4*)(g_s32 + (1ull << 20) + (size_t)n * 1024))[t];
    const int4 s2 = ((const int4*)(g_s32 + (2ull << 20) + (size_t)n * 1024))[t];
    const int4 s3 = ((const int4*)(g_s32 + (3ull << 20) + (size_t)n * 1024))[t];
    const float4 bb = ((const float4*)bf)[t];

    const double inv = 1.0 / 4294967296.0;
    char4 o;
    {
        long long S = ((long long)s0.x << 21) + ((long long)s1.x << 14)
                    + ((long long)s2.x << 7) + s3.x;
        o.x = (char)(int)fsign((float)((double)S * inv + (double)bb.x));
    }
    {
        long long S = ((long long)s0.y << 21) + ((long long)s1.y << 14)
                    + ((long long)s2.y << 7) + s3.y;
        o.y = (char)(int)fsign((float)((double)S * inv + (double)bb.y));
    }
    {
        long long S = ((long long)s0.z << 21) + ((long long)s1.z << 14)
                    + ((long long)s2.z << 7) + s3.z;
        o.z = (char)(int)fsign((float)((double)S * inv + (double)bb.z));
    }
    {
        long long S = ((long long)s0.w << 21) + ((long long)s1.w << 14)
                    + ((long long)s2.w << 7) + s3.w;
        o.w = (char)(int)fsign((float)((double)S * inv + (double)bb.w));
    }
    ((char4*)g_a3)[n * 256 + t] = o;
}

// ---------------------------------------------------------------------------
// Kernel 4: fc2  out[1024][10] = a3 @ W2^T + b2
// ---------------------------------------------------------------------------
__global__ __launch_bounds__(128) void k_fc2(
    const float* __restrict__ W2, const float* __restrict__ b2,
    float* __restrict__ out)
{
    const int n = blockIdx.x, tid = threadIdx.x;
    float acc[10] = {};
    const int8_t* a = g_a3 + n * 1024;
    for (int k = tid; k < 1024; k += 128) {
        float s = (float)a[k];
#pragma unroll
        for (int j = 0; j < 10; j++) acc[j] += s * W2[j * 1024 + k];
    }
#pragma unroll
    for (int j = 0; j < 10; j++)
#pragma unroll
        for (int off = 16; off; off >>= 1)
            acc[j] += __shfl_down_sync(0xffffffffu, acc[j], off);

    __shared__ float red[4][10];
    int w = tid >> 5, lm = tid & 31;
    if (lm == 0)
#pragma unroll
        for (int j = 0; j < 10; j++) red[w][j] = acc[j];
    __syncthreads();
    if (tid < 10) {
        float v = red[0][tid] + red[1][tid] + red[2][tid] + red[3][tid] + b2[tid];
        out[n * 10 + tid] = v;
    }
}

// ---------------------------------------------------------------------------
extern "C" void kernel_launch(void* const* d_in, const int* in_sizes, int n_in,
                              void* d_out, int out_size)
{
    const float* x    = (const float*)d_in[0];
    const float* w1dw = (const float*)d_in[1];
    const float* b1dw = (const float*)d_in[2];
    const float* w1pw = (const float*)d_in[3];
    const float* b1pw = (const float*)d_in[4];
    const float* w2dw = (const float*)d_in[5];
    const float* b2dw = (const float*)d_in[6];
    const float* w2pw = (const float*)d_in[7];
    const float* b2pw = (const float*)d_in[8];
    const float* fc1w = (const float*)d_in[9];
    const float* fc1b = (const float*)d_in[10];
    const float* fc2w = (const float*)d_in[11];
    const float* fc2b = (const float*)d_in[12];
    float* out = (float*)d_out;

    const int SMEM2 = 99840;
    cudaFuncSetAttribute(k_conv2, cudaFuncAttributeMaxDynamicSharedMemorySize, SMEM2);
    const int SMEMG = 4 * ST_SZ;   // 196608
    cudaFuncSetAttribute(k_fc1imma, cudaFuncAttributeMaxDynamicSharedMemorySize, SMEMG);

    k_wsplit<<<16384, 256>>>(fc1w);
    k_conv1<<<1024, 256>>>(x, w1dw, b1dw, w1pw, b1pw);
    k_conv2<<<1024, 256, SMEM2>>>(w2dw, b2dw, w2pw, b2pw);
    k_fc1imma<<<dim3(16, 8), 256, SMEMG>>>();
    k_fc1red<<<1024, 256>>>(fc1b);
    k_fc2<<<1024, 128>>>(fc2w, fc2b, out);
}